// round 9
// baseline (speedup 1.0000x reference)
#include <cuda_runtime.h>
#include <math.h>

#define Bv  4
#define Nn  24
#define NTT 16
#define TSS 48
#define TT  64
#define THR 384
#define NL  (Nn - 1)          // 23 l-slots per batch
#define SNAN 0x7fc00000u      // Ssc "not ready" sentinel

typedef unsigned long long u64;

// ---- packed fp32x2 helpers (sm_103a) ----
__device__ __forceinline__ u64 ffma2(u64 a, u64 b, u64 c) {
    u64 d;
    asm("fma.rn.f32x2 %0, %1, %2, %3;" : "=l"(d) : "l"(a), "l"(b), "l"(c));
    return d;
}
__device__ __forceinline__ u64 fadd2(u64 a, u64 b) {
    u64 d;
    asm("add.rn.f32x2 %0, %1, %2;" : "=l"(d) : "l"(a), "l"(b));
    return d;
}
__device__ __forceinline__ u64 pack2(float x, float y) {
    u64 d;
    asm("mov.b64 %0, {%1, %2};" : "=l"(d) : "f"(x), "f"(y));
    return d;
}
__device__ __forceinline__ float2 unpack2(u64 v) {
    float2 f;
    asm("mov.b64 {%0, %1}, %2;" : "=f"(f.x), "=f"(f.y) : "l"(v));
    return f;
}

// ---- fast exp: magic-number round + deg-5 Taylor on [-0.5, 0.5] (rel err ~2.4e-6) ----
__device__ __forceinline__ float fexp(float x) {
    x = fmaxf(x, -80.f);
    float k  = fmaf(x, 1.4426950408889634f, 12582912.f);
    int   n  = __float_as_int(k) - 0x4B400000;
    float nf = k - 12582912.f;
    float f  = fmaf(x, 1.4426950408889634f, -nf);
    float p  = 0.0013333558f;
    p = fmaf(p, f, 0.0096181291f);
    p = fmaf(p, f, 0.0555041086f);
    p = fmaf(p, f, 0.2402265069f);
    p = fmaf(p, f, 0.6931471806f);
    p = fmaf(p, f, 1.0f);
    return p * __int_as_float((n + 127) << 23);
}

// ---------------- device scratch ----------------
__device__ __align__(16) float d_E0t [Bv][Nn][256][NTT];   // exp(R0) as [b][h][sc=s*16+c][a]
__device__ __align__(16) float d_E1t [Bv][Nn][256][NTT];
__device__ float d_U0t [Bv][Nn][Nn][NTT][NTT];       // [b][h][k][s][a]
__device__ float d_U1t [Bv][Nn][Nn][NTT][NTT];       // [b][h][k][c][a]
__device__ float d_V0t [Bv][Nn][TT][NTT];            // [b][h][c][a]
__device__ float d_V1t [Bv][Nn][TT][NTT];            // [b][h][s][a]
__device__ float d_beta [Bv][Nn+1][Nn+1][NTT][Nn];
__device__ float d_betau[Bv][Nn+1][Nn+1][NTT];
__device__ float d_Ssc  [Bv][Nn+1][Nn+1];

// ---------------- kernel 1: rule precompute + Ssc sentinel fill ----------------
__global__ void __launch_bounds__(256) k_pre(const float* __restrict__ rule,
                                             const float* __restrict__ unary) {
    int blk = blockIdx.x;
    int h = blk % Nn;
    int a = (blk / Nn) % NTT;
    int b = blk / (Nn * NTT);
    const float2* R2 = (const float2*)(rule + (size_t)((b * NTT + a) * Nn + h) * (TT * TT * 2));

    __shared__ float Er0[TT][TT];
    __shared__ float Er1[TT][TT];
    __shared__ float eus[Nn][49];
    int tid = threadIdx.x;

    if (blk == 0) {  // sentinel-fill Ssc (doubles as dataflow flag); stream-ordered before k_chart
        for (int i = tid; i < Bv * (Nn + 1) * (Nn + 1); i += 256)
            ((unsigned*)&d_Ssc[0][0][0])[i] = SNAN;
    }

    for (int e = tid; e < TT * TT; e += 256) {
        float2 v = R2[e];
        int s = e >> 6, c = e & 63;
        Er0[s][c] = fexp(v.x);
        Er1[s][c] = fexp(v.y);
    }
    for (int t = tid; t < Nn * TSS; t += 256) {
        int k = t / TSS, c = t % TSS;
        eus[k][c] = fexp(unary[(b * Nn + k) * TT + NTT + c]);
    }
    __syncthreads();

    // E tables (NT x NT corner), fp32 [sc][a]
    {
        int s = tid >> 4, c = tid & 15;
        d_E0t[b][h][s * 16 + c][a] = Er0[s][c];
        d_E1t[b][h][s * 16 + c][a] = Er1[s][c];
    }
    if (tid < 128) {
        int x = tid & 63;
        float acc = 0.f;
        if (tid < 64) {
            #pragma unroll 8
            for (int s = NTT; s < TT; s++) acc += Er0[s][x];
            d_V0t[b][h][x][a] = acc;
        } else {
            #pragma unroll 8
            for (int c = NTT; c < TT; c++) acc += Er1[x][c];
            d_V1t[b][h][x][a] = acc;
        }
    }
    if (tid < 192) {
        int which = tid / 96;
        int g = tid % 96;
        int x = g & 15, k0 = (g >> 4) * 4;
        float a0 = 0.f, a1 = 0.f, a2 = 0.f, a3 = 0.f;
        if (which == 0) {
            #pragma unroll 8
            for (int c = 0; c < TSS; c++) {
                float e = Er0[x][NTT + c];
                a0 += e * eus[k0 + 0][c];
                a1 += e * eus[k0 + 1][c];
                a2 += e * eus[k0 + 2][c];
                a3 += e * eus[k0 + 3][c];
            }
            d_U0t[b][h][k0 + 0][x][a] = a0;
            d_U0t[b][h][k0 + 1][x][a] = a1;
            d_U0t[b][h][k0 + 2][x][a] = a2;
            d_U0t[b][h][k0 + 3][x][a] = a3;
        } else {
            #pragma unroll 8
            for (int s = 0; s < TSS; s++) {
                float e = Er1[NTT + s][x];
                a0 += e * eus[k0 + 0][s];
                a1 += e * eus[k0 + 1][s];
                a2 += e * eus[k0 + 2][s];
                a3 += e * eus[k0 + 3][s];
            }
            d_U1t[b][h][k0 + 0][x][a] = a0;
            d_U1t[b][h][k0 + 1][x][a] = a1;
            d_U1t[b][h][k0 + 2][x][a] = a2;
            d_U1t[b][h][k0 + 3][x][a] = a3;
        }
    }
}

// spin until Ssc value is published (not sentinel); integer compare = fast-math safe
__device__ __forceinline__ float spin_ssc(const float* p) {
    float v = *(volatile const float*)p;
    while (__float_as_uint(v) == SNAN) {
        __nanosleep(20);
        v = *(volatile const float*)p;
    }
    return v;
}

// ---------------- kernel 2: dataflow chart kernel ----------------
__global__ void __launch_bounds__(THR, 1) k_chart(const float* __restrict__ unary,
                                                  const float* __restrict__ root,
                                                  float* __restrict__ out) {
    extern __shared__ float dyn[];
    float* P0f  = dyn;                       // [24][264] fp32, row = hh
    float* P1f  = dyn + 24 * 264;            // [24][264]
    float* ownB = dyn + 2 * 24 * 264;        // [23][16][24] fp32, slot = width-2
    __shared__ float eu_s[Nn][TT];
    __shared__ __align__(16) float wRTi[NTT][24][2];   // [c][jj]{w0 (pairs bvL), w1 (pairs bvR)}
    __shared__ float BL2s[NTT][Nn];
    __shared__ float tmpsm[NTT][Nn];
    __shared__ float ownBu[Nn][NTT];   // slot = width-2
    __shared__ float ownS[Nn + 1];     // own Ssc by width
    __shared__ float wspe[Nn];
    __shared__ float buR0s[NTT];       // wspe[0]   * betau(l+1, r)
    __shared__ float buLW[NTT];        // wspe[W-2] * ownBu(l, r-1)
    __shared__ float red[12];
    __shared__ float sref_s, Msm_s;

    int tid = threadIdx.x;
    int b = blockIdx.x / NL;
    int l = blockIdx.x % NL;

    for (int t = tid; t < Nn * TT; t += THR)
        (&eu_s[0][0])[t] = fexp(unary[b * Nn * TT + t]);
    for (int t = tid; t < 8832; t += THR) ownB[t] = 0.f;
    if (tid < 2) ownS[tid] = 0.f;
    __syncthreads();

    int Wmax = Nn - l;
    for (int W = 2; W <= Wmax; W++) {
        int r = l + W;
        int nT = NTT * W;
        int a = tid & 15, hh = tid >> 4;

        if (W >= 3) {
            // ---- phase 1: warp 0 spins on right children, computes split weights ----
            if (tid < 32) {
                int j = tid;
                float v = -1e30f;
                if (j <= W - 2) {
                    float sl = (j == 0)     ? 0.f : ownS[j + 1];
                    float sr = (j == W - 2) ? 0.f : spin_ssc(&d_Ssc[b][l + 1 + j][r]);
                    v = sl + sr;
                }
                __threadfence();   // acquire
                float mx = v;
                #pragma unroll
                for (int o = 16; o > 0; o >>= 1) mx = fmaxf(mx, __shfl_xor_sync(0xffffffffu, mx, o));
                if (j <= W - 2) wspe[j] = expf(v - mx);
                if (j == 0) sref_s = mx;
            }
            __syncthreads();

            // ---- phase 2: interleaved weight tables + boundary child data ----
            {
                int c = tid / 24, jj = tid % 24;   // THR == 16*24
                int j = jj + 1;
                bool in = (j <= W - 3);
                wRTi[c][jj][0] = in ? wspe[j] * __ldcg(&d_betau[b][l + 1 + j][r][c]) : 0.f;
                wRTi[c][jj][1] = in ? wspe[j] * ownBu[j - 1][c] : 0.f;
            }
            if (tid < nT) {
                int c2 = tid / W, h2 = tid % W;
                BL2s[c2][h2] = __ldcg(&d_beta[b][l + 1][r][c2][l + h2]);
            }
            if (tid >= 352) {
                int c = tid - 352;
                if (c < NTT) {
                    buR0s[c] = wspe[0] * __ldcg(&d_betau[b][l + 1][r][c]);
                    buLW[c]  = wspe[W - 2] * ownBu[W - 3][c];
                }
            }
            __syncthreads();
        } else {
            if (tid == 0) sref_s = 0.f;
            __syncthreads();
        }

        if (W >= 4) {
            // ---- P build (both tables fused via FFMA2) ----
            if (tid < nT) {
                int phh = tid % W, x = tid / W;
                u64 bvp[24];
                #pragma unroll
                for (int j = 1; j <= 24; j++) {
                    if (j <= W - 3) {
                        float bl = ownB[(j - 1) * 384 + x * 24 + phh];
                        float br = __ldcg(&d_beta[b][l + 1 + j][r][x][l + phh]);
                        bvp[j - 1] = pack2(bl, br);
                    } else bvp[j - 1] = 0ULL;
                }
                #pragma unroll
                for (int c = 0; c < NTT; c++) {
                    u64 acc = 0ULL;
                    #pragma unroll
                    for (int k = 0; k < 6; k++) {
                        if (4 * k <= W - 4) {   // warp-uniform
                            const u64* wp = reinterpret_cast<const u64*>(&wRTi[c][4 * k][0]);
                            acc = ffma2(bvp[4 * k + 0], wp[0], acc);
                            acc = ffma2(bvp[4 * k + 1], wp[1], acc);
                            acc = ffma2(bvp[4 * k + 2], wp[2], acc);
                            acc = ffma2(bvp[4 * k + 3], wp[3], acc);
                        }
                    }
                    float2 pv = unpack2(acc);
                    P0f[phh * 264 + x * 16 + c] = pv.x;
                    P1f[phh * 264 + c * 16 + x] = pv.y;
                }
            }
            __syncthreads();

            // ---- contraction: warp per hh; lane = (sc_lo*2 + a8); fp32 E, FFMA2 ----
            {
                int wd = tid >> 5, lane = tid & 31;
                int sc_lo = lane >> 1, a8 = lane & 1;
                for (int chh = wd; chh < W; chh += 12) {
                    const float4* E0 = reinterpret_cast<const float4*>(d_E0t[b][l + chh]);
                    const float4* E1 = reinterpret_cast<const float4*>(d_E1t[b][l + chh]);
                    const float* p0 = P0f + chh * 264;
                    const float* p1 = P1f + chh * 264;
                    u64 acc0 = 0ULL, acc1 = 0ULL, acc2 = 0ULL, acc3 = 0ULL;
                    #pragma unroll
                    for (int i = 0; i < 16; i++) {
                        int sc = i * 16 + sc_lo;
                        u64 v0 = pack2(p0[sc], p0[sc]);
                        u64 v1 = pack2(p1[sc], p1[sc]);
                        float4 e0a = __ldg(E0 + sc * 4 + a8 * 2 + 0);
                        float4 e0b = __ldg(E0 + sc * 4 + a8 * 2 + 1);
                        float4 e1a = __ldg(E1 + sc * 4 + a8 * 2 + 0);
                        float4 e1b = __ldg(E1 + sc * 4 + a8 * 2 + 1);
                        const u64* q0a = reinterpret_cast<const u64*>(&e0a);
                        const u64* q0b = reinterpret_cast<const u64*>(&e0b);
                        const u64* q1a = reinterpret_cast<const u64*>(&e1a);
                        const u64* q1b = reinterpret_cast<const u64*>(&e1b);
                        acc0 = ffma2(v0, q0a[0], acc0);
                        acc1 = ffma2(v0, q0a[1], acc1);
                        acc2 = ffma2(v0, q0b[0], acc2);
                        acc3 = ffma2(v0, q0b[1], acc3);
                        acc0 = ffma2(v1, q1a[0], acc0);
                        acc1 = ffma2(v1, q1a[1], acc1);
                        acc2 = ffma2(v1, q1b[0], acc2);
                        acc3 = ffma2(v1, q1b[1], acc3);
                    }
                    #pragma unroll
                    for (int o = 2; o <= 16; o <<= 1) {
                        acc0 = fadd2(acc0, __shfl_xor_sync(0xffffffffu, acc0, o));
                        acc1 = fadd2(acc1, __shfl_xor_sync(0xffffffffu, acc1, o));
                        acc2 = fadd2(acc2, __shfl_xor_sync(0xffffffffu, acc2, o));
                        acc3 = fadd2(acc3, __shfl_xor_sync(0xffffffffu, acc3, o));
                    }
                    if (lane < 2) {
                        int ab = lane * 8;
                        float2 f;
                        f = unpack2(acc0); tmpsm[ab + 0][chh] = f.x; tmpsm[ab + 1][chh] = f.y;
                        f = unpack2(acc1); tmpsm[ab + 2][chh] = f.x; tmpsm[ab + 3][chh] = f.y;
                        f = unpack2(acc2); tmpsm[ab + 4][chh] = f.x; tmpsm[ab + 5][chh] = f.y;
                        f = unpack2(acc3); tmpsm[ab + 6][chh] = f.x; tmpsm[ab + 7][chh] = f.y;
                    }
                }
            }
            __syncthreads();
        }

        // ---- boundary terms + assemble tval ----
        float tval = 0.f;
        if (tid < nT) {
            if (W >= 3) {
                if (W >= 4) tval = tmpsm[a][hh];
                float s2 = 0.f, s3 = 0.f;
                #pragma unroll
                for (int c = 0; c < NTT; c++) {
                    s2 += __ldg(&d_U1t[b][l + hh][l][c][a]) * BL2s[c][hh];
                    s3 += __ldg(&d_U0t[b][l + hh][r - 1][c][a]) * ownB[(W - 3) * 384 + c * 24 + hh];
                }
                tval += wspe[0] * s2 + wspe[W - 2] * s3;
                if (hh == 0) {
                    float s1 = 0.f;
                    #pragma unroll
                    for (int c = 0; c < NTT; c++)
                        s1 += __ldg(&d_V0t[b][l][c][a]) * buR0s[c];
                    tval += s1;
                }
                if (hh == W - 1) {
                    float s4 = 0.f;
                    #pragma unroll
                    for (int c = 0; c < NTT; c++)
                        s4 += __ldg(&d_V1t[b][r - 1][c][a]) * buLW[c];
                    tval += s4;
                }
            } else {  // W == 2: both children width-1, scale 0
                if (hh == 0) {
                    #pragma unroll 8
                    for (int c = 0; c < TSS; c++)
                        tval += eu_s[l + 1][NTT + c] * __ldg(&d_V0t[b][l][NTT + c][a]);
                } else {
                    #pragma unroll 8
                    for (int c = 0; c < TSS; c++)
                        tval += eu_s[l][NTT + c] * __ldg(&d_V1t[b][l + 1][NTT + c][a]);
                }
            }
        }

        // ---- max, rescale, commit, publish (Ssc last = release flag) ----
        float vmax = 0.f;
        if (tid < nT) {
            tmpsm[a][hh] = tval;
            vmax = tval;
        }
        #pragma unroll
        for (int o = 16; o > 0; o >>= 1) vmax = fmaxf(vmax, __shfl_xor_sync(0xffffffffu, vmax, o));
        if ((tid & 31) == 0) red[tid >> 5] = vmax;
        __syncthreads();
        if (tid < 32) {
            float v = (tid < 12) ? red[tid] : 0.f;
            #pragma unroll
            for (int o = 8; o > 0; o >>= 1) v = fmaxf(v, __shfl_xor_sync(0xffffffffu, v, o));
            if (tid == 0) Msm_s = v;
        }
        __syncthreads();
        float invM = 1.f / Msm_s;
        {
            int ca = tid / Nn, habs = tid % Nn;   // THR == 16*24 exactly
            float v = 0.f;
            if (habs >= l && habs < r) {
                v = tmpsm[ca][habs - l] * invM;
                ownB[(W - 2) * 384 + ca * 24 + (habs - l)] = v;
            }
            __stcg(&d_beta[b][l][r][ca][habs], v);
        }
        if (tid < NTT) {
            float accu = 0.f;
            for (int h2 = 0; h2 < W; h2++)
                accu += tmpsm[tid][h2] * eu_s[l + h2][tid];
            float bu = accu * invM;
            __stcg(&d_betau[b][l][r][tid], bu);
            ownBu[W - 2][tid] = bu;
            if (W == Nn) {   // only block (b, 0): fused root reduction
                float v = bu * __expf(root[b * NTT + tid]);
                #pragma unroll
                for (int o = 8; o > 0; o >>= 1) v += __shfl_xor_sync(0xffffu, v, o);
                if (tid == 0) out[b] = sref_s + logf(Msm_s) + logf(v);
            }
        }
        __threadfence();   // make beta/betau visible before Ssc (the flag)
        __syncthreads();
        if (tid == 0) {
            float ss = sref_s + logf(Msm_s);
            ownS[W] = ss;
            __stcg(&d_Ssc[b][l][r], ss);
        }
        __syncthreads();
    }
}

// ---------------- launch ----------------
extern "C" void kernel_launch(void* const* d_in, const int* in_sizes, int n_in,
                              void* d_out, int out_size) {
    const float* unary = nullptr;
    const float* rule  = nullptr;
    const float* root  = nullptr;
    for (int i = 0; i < n_in; i++) {
        if (in_sizes[i] == Bv * Nn * TT)                      unary = (const float*)d_in[i];
        else if (in_sizes[i] == Bv * NTT * Nn * TT * TT * 2)  rule  = (const float*)d_in[i];
        else if (in_sizes[i] == Bv * NTT)                     root  = (const float*)d_in[i];
    }

    int dynBytes = (2 * 24 * 264 + 23 * 16 * 24) * (int)sizeof(float);  // 86016
    cudaFuncSetAttribute(k_chart, cudaFuncAttributeMaxDynamicSharedMemorySize, dynBytes);

    k_pre<<<Bv * NTT * Nn, 256>>>(rule, unary);
    k_chart<<<Bv * NL, THR, dynBytes>>>(unary, root, (float*)d_out);
}

// round 10
// speedup vs baseline: 1.1921x; 1.1921x over previous
#include <cuda_runtime.h>
#include <cuda_fp16.h>
#include <math.h>

#define Bv  4
#define Nn  24
#define NTT 16
#define TSS 48
#define TT  64
#define THR 384
#define NL  (Nn - 1)          // 23 l-slots per batch
#define SNAN 0x7fc00000u      // Ssc "not ready" sentinel
#define ESCALE 4096.0f
#define EINV   (1.0f / 4096.0f)

typedef unsigned long long u64;

// ---- packed fp32x2 helpers (sm_103a) ----
__device__ __forceinline__ u64 ffma2(u64 a, u64 b, u64 c) {
    u64 d;
    asm("fma.rn.f32x2 %0, %1, %2, %3;" : "=l"(d) : "l"(a), "l"(b), "l"(c));
    return d;
}
__device__ __forceinline__ u64 pack2(float x, float y) {
    u64 d;
    asm("mov.b64 %0, {%1, %2};" : "=l"(d) : "f"(x), "f"(y));
    return d;
}
__device__ __forceinline__ float2 unpack2(u64 v) {
    float2 f;
    asm("mov.b64 {%0, %1}, %2;" : "=f"(f.x), "=f"(f.y) : "l"(v));
    return f;
}

// ---- fast exp: magic-number round + deg-5 Taylor (rel err ~2.4e-6) ----
__device__ __forceinline__ float fexp(float x) {
    x = fmaxf(x, -80.f);
    float k  = fmaf(x, 1.4426950408889634f, 12582912.f);
    int   n  = __float_as_int(k) - 0x4B400000;
    float nf = k - 12582912.f;
    float f  = fmaf(x, 1.4426950408889634f, -nf);
    float p  = 0.0013333558f;
    p = fmaf(p, f, 0.0096181291f);
    p = fmaf(p, f, 0.0555041086f);
    p = fmaf(p, f, 0.2402265069f);
    p = fmaf(p, f, 0.6931471806f);
    p = fmaf(p, f, 1.0f);
    return p * __int_as_float((n + 127) << 23);
}

// ---------------- device scratch ----------------
__device__ __align__(16) __half d_E0h[Bv][Nn][256][NTT];   // exp(R0)*4096, [b][h][sc][a] fp16
__device__ __align__(16) __half d_E1h[Bv][Nn][256][NTT];
__device__ float d_U0t [Bv][Nn][Nn][NTT][NTT];       // [b][h][k][s][a]
__device__ float d_U1t [Bv][Nn][Nn][NTT][NTT];       // [b][h][k][c][a]
__device__ float d_V0t [Bv][Nn][TT][NTT];            // [b][h][c][a]
__device__ float d_V1t [Bv][Nn][TT][NTT];            // [b][h][s][a]
__device__ float d_beta [Bv][Nn+1][Nn+1][NTT][Nn];
__device__ float d_betau[Bv][Nn+1][Nn+1][NTT];
__device__ float d_Ssc  [Bv][Nn+1][Nn+1];

// ---------------- kernel 1: rule precompute + Ssc sentinel fill ----------------
__global__ void __launch_bounds__(256) k_pre(const float* __restrict__ rule,
                                             const float* __restrict__ unary) {
    int blk = blockIdx.x;
    int h = blk % Nn;
    int a = (blk / Nn) % NTT;
    int b = blk / (Nn * NTT);
    const float2* R2 = (const float2*)(rule + (size_t)((b * NTT + a) * Nn + h) * (TT * TT * 2));

    __shared__ float Er0[TT][TT];
    __shared__ float Er1[TT][TT];
    __shared__ float eus[Nn][49];
    int tid = threadIdx.x;

    if (blk == 0) {  // sentinel-fill Ssc (doubles as dataflow flag); stream-ordered before k_chart
        for (int i = tid; i < Bv * (Nn + 1) * (Nn + 1); i += 256)
            ((unsigned*)&d_Ssc[0][0][0])[i] = SNAN;
    }

    for (int e = tid; e < TT * TT; e += 256) {
        float2 v = R2[e];
        int s = e >> 6, c = e & 63;
        Er0[s][c] = fexp(v.x);
        Er1[s][c] = fexp(v.y);
    }
    for (int t = tid; t < Nn * TSS; t += 256) {
        int k = t / TSS, c = t % TSS;
        eus[k][c] = fexp(unary[(b * Nn + k) * TT + NTT + c]);
    }
    __syncthreads();

    // E tables: fp16, pre-scaled, layout [sc][a]
    {
        int s = tid >> 4, c = tid & 15;
        d_E0h[b][h][s * 16 + c][a] = __float2half_rn(Er0[s][c] * ESCALE);
        d_E1h[b][h][s * 16 + c][a] = __float2half_rn(Er1[s][c] * ESCALE);
    }
    if (tid < 128) {
        int x = tid & 63;
        float acc = 0.f;
        if (tid < 64) {
            #pragma unroll 8
            for (int s = NTT; s < TT; s++) acc += Er0[s][x];
            d_V0t[b][h][x][a] = acc;
        } else {
            #pragma unroll 8
            for (int c = NTT; c < TT; c++) acc += Er1[x][c];
            d_V1t[b][h][x][a] = acc;
        }
    }
    if (tid < 192) {
        int which = tid / 96;
        int g = tid % 96;
        int x = g & 15, k0 = (g >> 4) * 4;
        float a0 = 0.f, a1 = 0.f, a2 = 0.f, a3 = 0.f;
        if (which == 0) {
            #pragma unroll 8
            for (int c = 0; c < TSS; c++) {
                float e = Er0[x][NTT + c];
                a0 += e * eus[k0 + 0][c];
                a1 += e * eus[k0 + 1][c];
                a2 += e * eus[k0 + 2][c];
                a3 += e * eus[k0 + 3][c];
            }
            d_U0t[b][h][k0 + 0][x][a] = a0;
            d_U0t[b][h][k0 + 1][x][a] = a1;
            d_U0t[b][h][k0 + 2][x][a] = a2;
            d_U0t[b][h][k0 + 3][x][a] = a3;
        } else {
            #pragma unroll 8
            for (int s = 0; s < TSS; s++) {
                float e = Er1[NTT + s][x];
                a0 += e * eus[k0 + 0][s];
                a1 += e * eus[k0 + 1][s];
                a2 += e * eus[k0 + 2][s];
                a3 += e * eus[k0 + 3][s];
            }
            d_U1t[b][h][k0 + 0][x][a] = a0;
            d_U1t[b][h][k0 + 1][x][a] = a1;
            d_U1t[b][h][k0 + 2][x][a] = a2;
            d_U1t[b][h][k0 + 3][x][a] = a3;
        }
    }
}

// spin until Ssc value is published (not sentinel); integer compare = fast-math safe
__device__ __forceinline__ float spin_ssc(const float* p) {
    float v = *(volatile const float*)p;
    while (__float_as_uint(v) == SNAN) {
        __nanosleep(20);
        v = *(volatile const float*)p;
    }
    return v;
}

// ---------------- kernel 2: dataflow chart kernel ----------------
__global__ void __launch_bounds__(THR, 1) k_chart(const float* __restrict__ unary,
                                                  const float* __restrict__ root,
                                                  float* __restrict__ out) {
    extern __shared__ float dyn[];
    float* P0f  = dyn;                       // [24][264] fp32, row = hh, col = sc
    float* P1f  = dyn + 24 * 264;            // [24][264]
    float* ownB = dyn + 2 * 24 * 264;        // [23][16][24] fp32, slot = width-2
    __shared__ float eu_s[Nn][TT];
    __shared__ __align__(16) float wRTi[NTT][24][2];   // [c][jj]{w0, w1} interleaved
    __shared__ float BL2s[NTT][Nn];
    __shared__ float tmpsm[NTT][Nn];
    __shared__ float ownBu[Nn][NTT];   // slot = width-2
    __shared__ float ownS[Nn + 1];     // own Ssc by width
    __shared__ float wspe[Nn];
    __shared__ float buR0s[NTT];       // wspe[0]   * betau(l+1, r)
    __shared__ float buLW[NTT];        // wspe[W-2] * ownBu(l, r-1)
    __shared__ float red[12];
    __shared__ float sref_s, Msm_s;

    int tid = threadIdx.x;
    int b = blockIdx.x / NL;
    int l = blockIdx.x % NL;

    for (int t = tid; t < Nn * TT; t += THR)
        (&eu_s[0][0])[t] = fexp(unary[b * Nn * TT + t]);
    for (int t = tid; t < 8832; t += THR) ownB[t] = 0.f;
    if (tid < 2) ownS[tid] = 0.f;
    __syncthreads();

    int Wmax = Nn - l;
    for (int W = 2; W <= Wmax; W++) {
        int r = l + W;
        int nT = NTT * W;
        int a = tid & 15, hh = tid >> 4;

        if (W >= 3) {
            // ---- phase 1: warp 0 spins on right children, computes split weights ----
            if (tid < 32) {
                int j = tid;
                float v = -1e30f;
                if (j <= W - 2) {
                    float sl = (j == 0)     ? 0.f : ownS[j + 1];
                    float sr = (j == W - 2) ? 0.f : spin_ssc(&d_Ssc[b][l + 1 + j][r]);
                    v = sl + sr;
                }
                __threadfence();   // acquire
                float mx = v;
                #pragma unroll
                for (int o = 16; o > 0; o >>= 1) mx = fmaxf(mx, __shfl_xor_sync(0xffffffffu, mx, o));
                if (j <= W - 2) wspe[j] = expf(v - mx);
                if (j == 0) sref_s = mx;
            }
            __syncthreads();

            // ---- phase 2: interleaved weight tables + boundary child data ----
            {
                int c = tid / 24, jj = tid % 24;   // THR == 16*24
                int j = jj + 1;
                bool in = (j <= W - 3);
                wRTi[c][jj][0] = in ? wspe[j] * __ldcg(&d_betau[b][l + 1 + j][r][c]) : 0.f;
                wRTi[c][jj][1] = in ? wspe[j] * ownBu[j - 1][c] : 0.f;
            }
            if (tid < nT) {
                int c2 = tid / W, h2 = tid % W;
                BL2s[c2][h2] = __ldcg(&d_beta[b][l + 1][r][c2][l + h2]);
            }
            if (tid >= 352) {
                int c = tid - 352;
                if (c < NTT) {
                    buR0s[c] = wspe[0] * __ldcg(&d_betau[b][l + 1][r][c]);
                    buLW[c]  = wspe[W - 2] * ownBu[W - 3][c];
                }
            }
            __syncthreads();
        } else {
            if (tid == 0) sref_s = 0.f;
            __syncthreads();
        }

        if (W >= 4) {
            // ---- P build: both tables fused via FFMA2 ----
            if (tid < nT) {
                int phh = tid % W, x = tid / W;
                u64 bvp[24];
                #pragma unroll
                for (int j = 1; j <= 24; j++) {
                    if (j <= W - 3) {
                        float bl = ownB[(j - 1) * 384 + x * 24 + phh];
                        float br = __ldcg(&d_beta[b][l + 1 + j][r][x][l + phh]);
                        bvp[j - 1] = pack2(bl, br);
                    } else bvp[j - 1] = 0ULL;
                }
                #pragma unroll
                for (int c = 0; c < NTT; c++) {
                    u64 acc = 0ULL;
                    #pragma unroll
                    for (int k = 0; k < 6; k++) {
                        if (4 * k <= W - 4) {   // warp-uniform
                            const u64* wp = reinterpret_cast<const u64*>(&wRTi[c][4 * k][0]);
                            acc = ffma2(bvp[4 * k + 0], wp[0], acc);
                            acc = ffma2(bvp[4 * k + 1], wp[1], acc);
                            acc = ffma2(bvp[4 * k + 2], wp[2], acc);
                            acc = ffma2(bvp[4 * k + 3], wp[3], acc);
                        }
                    }
                    float2 pv = unpack2(acc);
                    P0f[phh * 264 + x * 16 + c] = pv.x;
                    P1f[phh * 264 + c * 16 + x] = pv.y;
                }
            }
            __syncthreads();

            // ---- contraction: warp per hh; lanes = (sc_lo 16, a8 2); fp16 E, fp32 accum ----
            {
                int wd = tid >> 5, lane = tid & 31;
                int sc_lo = lane >> 1, a8 = lane & 1;
                for (int chh = wd; chh < W; chh += 12) {
                    const uint4* E0 = reinterpret_cast<const uint4*>(&d_E0h[b][l + chh][0][0]);
                    const uint4* E1 = reinterpret_cast<const uint4*>(&d_E1h[b][l + chh][0][0]);
                    const float* p0 = P0f + chh * 264;
                    const float* p1 = P1f + chh * 264;
                    float acc[8];
                    #pragma unroll
                    for (int k = 0; k < 8; k++) acc[k] = 0.f;
                    #pragma unroll
                    for (int i = 0; i < 16; i++) {
                        int sc = i * 16 + sc_lo;
                        float v0 = p0[sc];
                        float v1 = p1[sc];
                        uint4 e0 = __ldg(E0 + sc * 2 + a8);
                        uint4 e1 = __ldg(E1 + sc * 2 + a8);
                        float2 f;
                        f = __half22float2(*reinterpret_cast<const __half2*>(&e0.x));
                        acc[0] = fmaf(v0, f.x, acc[0]); acc[1] = fmaf(v0, f.y, acc[1]);
                        f = __half22float2(*reinterpret_cast<const __half2*>(&e0.y));
                        acc[2] = fmaf(v0, f.x, acc[2]); acc[3] = fmaf(v0, f.y, acc[3]);
                        f = __half22float2(*reinterpret_cast<const __half2*>(&e0.z));
                        acc[4] = fmaf(v0, f.x, acc[4]); acc[5] = fmaf(v0, f.y, acc[5]);
                        f = __half22float2(*reinterpret_cast<const __half2*>(&e0.w));
                        acc[6] = fmaf(v0, f.x, acc[6]); acc[7] = fmaf(v0, f.y, acc[7]);
                        f = __half22float2(*reinterpret_cast<const __half2*>(&e1.x));
                        acc[0] = fmaf(v1, f.x, acc[0]); acc[1] = fmaf(v1, f.y, acc[1]);
                        f = __half22float2(*reinterpret_cast<const __half2*>(&e1.y));
                        acc[2] = fmaf(v1, f.x, acc[2]); acc[3] = fmaf(v1, f.y, acc[3]);
                        f = __half22float2(*reinterpret_cast<const __half2*>(&e1.z));
                        acc[4] = fmaf(v1, f.x, acc[4]); acc[5] = fmaf(v1, f.y, acc[5]);
                        f = __half22float2(*reinterpret_cast<const __half2*>(&e1.w));
                        acc[6] = fmaf(v1, f.x, acc[6]); acc[7] = fmaf(v1, f.y, acc[7]);
                    }
                    #pragma unroll
                    for (int o = 2; o <= 16; o <<= 1) {
                        #pragma unroll
                        for (int k = 0; k < 8; k++)
                            acc[k] += __shfl_xor_sync(0xffffffffu, acc[k], o);
                    }
                    if (sc_lo == 0) {
                        int abase = a8 * 8;
                        #pragma unroll
                        for (int k = 0; k < 8; k++)
                            tmpsm[abase + k][chh] = acc[k] * EINV;
                    }
                }
            }
            __syncthreads();
        }

        // ---- boundary terms + assemble tval ----
        float tval = 0.f;
        if (tid < nT) {
            if (W >= 3) {
                if (W >= 4) tval = tmpsm[a][hh];
                float s2 = 0.f, s3 = 0.f;
                #pragma unroll
                for (int c = 0; c < NTT; c++) {
                    s2 += __ldg(&d_U1t[b][l + hh][l][c][a]) * BL2s[c][hh];
                    s3 += __ldg(&d_U0t[b][l + hh][r - 1][c][a]) * ownB[(W - 3) * 384 + c * 24 + hh];
                }
                tval += wspe[0] * s2 + wspe[W - 2] * s3;
                if (hh == 0) {
                    float s1 = 0.f;
                    #pragma unroll
                    for (int c = 0; c < NTT; c++)
                        s1 += __ldg(&d_V0t[b][l][c][a]) * buR0s[c];
                    tval += s1;
                }
                if (hh == W - 1) {
                    float s4 = 0.f;
                    #pragma unroll
                    for (int c = 0; c < NTT; c++)
                        s4 += __ldg(&d_V1t[b][r - 1][c][a]) * buLW[c];
                    tval += s4;
                }
            } else {  // W == 2: both children width-1, scale 0
                if (hh == 0) {
                    #pragma unroll 8
                    for (int c = 0; c < TSS; c++)
                        tval += eu_s[l + 1][NTT + c] * __ldg(&d_V0t[b][l][NTT + c][a]);
                } else {
                    #pragma unroll 8
                    for (int c = 0; c < TSS; c++)
                        tval += eu_s[l][NTT + c] * __ldg(&d_V1t[b][l + 1][NTT + c][a]);
                }
            }
        }

        // ---- max, rescale, commit, publish (Ssc last = release flag) ----
        float vmax = 0.f;
        if (tid < nT) {
            tmpsm[a][hh] = tval;
            vmax = tval;
        }
        #pragma unroll
        for (int o = 16; o > 0; o >>= 1) vmax = fmaxf(vmax, __shfl_xor_sync(0xffffffffu, vmax, o));
        if ((tid & 31) == 0) red[tid >> 5] = vmax;
        __syncthreads();
        if (tid < 32) {
            float v = (tid < 12) ? red[tid] : 0.f;
            #pragma unroll
            for (int o = 8; o > 0; o >>= 1) v = fmaxf(v, __shfl_xor_sync(0xffffffffu, v, o));
            if (tid == 0) Msm_s = v;
        }
        __syncthreads();
        float invM = 1.f / Msm_s;
        {
            int ca = tid / Nn, habs = tid % Nn;   // THR == 16*24 exactly
            float v = 0.f;
            if (habs >= l && habs < r) {
                v = tmpsm[ca][habs - l] * invM;
                ownB[(W - 2) * 384 + ca * 24 + (habs - l)] = v;
            }
            __stcg(&d_beta[b][l][r][ca][habs], v);
        }
        if (tid < NTT) {
            float accu = 0.f;
            for (int h2 = 0; h2 < W; h2++)
                accu += tmpsm[tid][h2] * eu_s[l + h2][tid];
            float bu = accu * invM;
            __stcg(&d_betau[b][l][r][tid], bu);
            ownBu[W - 2][tid] = bu;
            if (W == Nn) {   // only block (b, 0): fused root reduction
                float v = bu * __expf(root[b * NTT + tid]);
                #pragma unroll
                for (int o = 8; o > 0; o >>= 1) v += __shfl_xor_sync(0xffffu, v, o);
                if (tid == 0) out[b] = sref_s + logf(Msm_s) + logf(v);
            }
        }
        __threadfence();   // make beta/betau visible before Ssc (the flag)
        __syncthreads();
        if (tid == 0) {
            float ss = sref_s + logf(Msm_s);
            ownS[W] = ss;
            __stcg(&d_Ssc[b][l][r], ss);
        }
        __syncthreads();
    }
}

// ---------------- launch ----------------
extern "C" void kernel_launch(void* const* d_in, const int* in_sizes, int n_in,
                              void* d_out, int out_size) {
    const float* unary = nullptr;
    const float* rule  = nullptr;
    const float* root  = nullptr;
    for (int i = 0; i < n_in; i++) {
        if (in_sizes[i] == Bv * Nn * TT)                      unary = (const float*)d_in[i];
        else if (in_sizes[i] == Bv * NTT * Nn * TT * TT * 2)  rule  = (const float*)d_in[i];
        else if (in_sizes[i] == Bv * NTT)                     root  = (const float*)d_in[i];
    }

    int dynBytes = (2 * 24 * 264 + 23 * 16 * 24) * (int)sizeof(float);  // 86016
    cudaFuncSetAttribute(k_chart, cudaFuncAttributeMaxDynamicSharedMemorySize, dynBytes);

    k_pre<<<Bv * NTT * Nn, 256>>>(rule, unary);
    k_chart<<<Bv * NL, THR, dynBytes>>>(unary, root, (float*)d_out);
}